// round 13
// baseline (speedup 1.0000x reference)
#include <cuda_runtime.h>
#include <cstdint>

// ---------------- problem constants ----------------
#define BATCH   2
#define NPTS    110592            // 48^3
#define BN      (BATCH * NPTS)    // 221184
#define NF      256
#define NM      16
#define NCHUNK  432               // chunks per batch
#define CHUNK   256               // points per CTA (432 * 256 = 110592)
#define NPB     (CHUNK / 8)       // 32 point-blocks of 8
#define TWO_PI_F 6.283185307179586f
#define INV_SQRT_N 0.0030070286f  // 1/sqrt(110592)

#define NOUT       (BATCH * NF * NM)       // 8192 complex elements
#define OUT_FLOATS (NOUT * 2)              // 16384

// reduction tree: 432 = 27 * 16
#define R1_GROUPS  27
#define R1_CH      16

#define SZ_A   (BN * 16)
#define SZ_X   (BN * 3)
#define SZ_AW  (16 * 16)
#define SZ_XW  (3 * 256)

// SMEM layout (floats): aw[256] | xraw[768] | x4[1024] | A[4096]
#define SMF_AW  0
#define SMF_XR  256
#define SMF_X4  (256 + 768)
#define SMF_A   (256 + 768 + 1024)
#define SMEM_BYTES ((256 + 768 + 1024 + 4096) * 4)   // 24576

// ---------------- device scratch (no allocation allowed) ----------------
__device__ float g_part[NCHUNK * OUT_FLOATS];     // per-chunk planar partials (28.3 MB)
__device__ float g_p2[R1_GROUPS * OUT_FLOATS];    // stage-1 partials (1.8 MB)

// ---------------- helpers ----------------
__device__ __forceinline__ uint32_t tf32r(float f) {
    uint32_t r;
    asm("cvt.rna.tf32.f32 %0, %1;" : "=r"(r) : "f"(f));
    return r;
}
__device__ __forceinline__ void mma_tf32(float* d, const uint32_t* a, const uint32_t* b) {
    asm volatile(
        "mma.sync.aligned.m16n8k8.row.col.f32.tf32.tf32.f32 "
        "{%0,%1,%2,%3}, {%4,%5,%6,%7}, {%8,%9}, {%0,%1,%2,%3};"
        : "+f"(d[0]), "+f"(d[1]), "+f"(d[2]), "+f"(d[3])
        : "r"(a[0]), "r"(a[1]), "r"(a[2]), "r"(a[3]), "r"(b[0]), "r"(b[1]));
}

// ---------- fused kernel: stage + project + sincos + tf32 MMA ----------
// grid = (NCHUNK, BATCH*2). blockIdx.y: bit0 = f-half, bit1 = batch.
// 256 threads; each warp owns ONE 16-f tile. Target 4 CTAs/SM.
__global__ void __launch_bounds__(256, 4) spectral_main(const float* __restrict__ a,
                                                        const float* __restrict__ x,
                                                        const float* __restrict__ aw,
                                                        const float* __restrict__ xw) {
    extern __shared__ float sm[];
    float*  s_aw = sm + SMF_AW;             // 16x16 row-major [i][m]
    float*  s_xr = sm + SMF_XR;             // 256 x 3 raw
    float4* s_x4 = (float4*)(sm + SMF_X4);  // 256 x float4 (padded)
    float*  s_A  = sm + SMF_A;              // 256 x 16, tf32-rounded scaled coefficients

    const int tid  = threadIdx.x;
    const int lane = tid & 31;
    const int warp = tid >> 5;
    const int by   = blockIdx.y;
    const int b    = by >> 1;
    const int fh   = by & 1;
    const int chunk = blockIdx.x;
    const size_t pbase = (size_t)(b * NPTS + chunk * CHUNK);

    // ---- stage: aw, raw a-chunk (16KB), raw x-chunk (3KB), all coalesced ----
    s_aw[tid] = aw[tid];
    {
        const float4* ga = (const float4*)(a + pbase * 16);   // 1024 float4
        float4* sa4 = (float4*)s_A;
#pragma unroll
        for (int i = 0; i < 4; ++i) sa4[tid + 256 * i] = ga[tid + 256 * i];
        const float4* gx = (const float4*)(x + pbase * 3);    // 192 float4
        float4* sx4 = (float4*)s_xr;
        if (tid < 192) sx4[tid] = gx[tid];
    }
    __syncthreads();

    // ---- pad x to float4: one point per thread ----
    {
        float r0 = s_xr[tid * 3 + 0], r1 = s_xr[tid * 3 + 1], r2 = s_xr[tid * 3 + 2];
        s_x4[tid] = make_float4(r0, r1, r2, 0.0f);
    }

    // ---- in-place projection: A[p][m] = tf32(sum_i a[p][i]*aw[i][m] * inv_sqrt_n)
    {
        int p = tid;                         // 1 row per thread
        float ai[16];
#pragma unroll
        for (int i = 0; i < 16; ++i) ai[i] = s_A[p * 16 + i];
        float o[16];
#pragma unroll
        for (int m = 0; m < 16; ++m) o[m] = 0.0f;
#pragma unroll
        for (int i = 0; i < 16; ++i)
#pragma unroll
            for (int m = 0; m < 16; ++m)
                o[m] = fmaf(ai[i], s_aw[i * 16 + m], o[m]);
#pragma unroll
        for (int m = 0; m < 16; ++m)
            s_A[p * 16 + m] = __uint_as_float(tf32r(o[m] * INV_SQRT_N));
    }
    __syncthreads();

    // ---- this warp's f-tile: f = fbase + (lane>>2) and +8 ----
    const int fbase = (fh * 8 + warp) * 16;
    const int g  = lane >> 2;
    const int f0 = fbase + g;
    const int f1 = f0 + 8;
    float W0[3], W1[3];
#pragma unroll
    for (int d = 0; d < 3; ++d) {
        W0[d] = TWO_PI_F * xw[d * NF + f0];
        W1[d] = TWO_PI_F * xw[d * NF + f1];
    }

    float accR0[4], accR1[4], accI0[4], accI1[4];   // mhalf 0 / 1
#pragma unroll
    for (int k = 0; k < 4; ++k) { accR0[k] = accR1[k] = accI0[k] = accI1[k] = 0.0f; }

    const int kp = lane & 3;        // k-position within point-block
    const int m0 = lane >> 2;       // m channel for B fragment

    for (int pb = 0; pb < NPB; ++pb) {
        const int p0 = pb * 8 + kp;
        float4 xv0 = s_x4[p0];          // LDS.128, 4-way broadcast groups
        float4 xv1 = s_x4[p0 + 4];

        // 4 phases: (f0,pt0) (f0,pt1) (f1,pt0) (f1,pt1)
        float c00, s00, c01, s01, c10, s10, c11, s11;
        {
            float ph;
            ph = fmaf(xv0.x, W0[0], fmaf(xv0.y, W0[1], xv0.z * W0[2]));
            __sincosf(ph, &s00, &c00);
            ph = fmaf(xv1.x, W0[0], fmaf(xv1.y, W0[1], xv1.z * W0[2]));
            __sincosf(ph, &s01, &c01);
            ph = fmaf(xv0.x, W1[0], fmaf(xv0.y, W1[1], xv0.z * W1[2]));
            __sincosf(ph, &s10, &c10);
            ph = fmaf(xv1.x, W1[0], fmaf(xv1.y, W1[1], xv1.z * W1[2]));
            __sincosf(ph, &s11, &c11);
        }

        // A fragments: a0=(g,kp) a1=(g+8,kp) a2=(g,kp+4) a3=(g+8,kp+4)
        uint32_t fc[4] = { __float_as_uint(c00), __float_as_uint(c10),
                           __float_as_uint(c01), __float_as_uint(c11) };
        uint32_t fs[4] = { __float_as_uint(s00), __float_as_uint(s10),
                           __float_as_uint(s01), __float_as_uint(s11) };

        // B fragments: b0=(k=kp, n=m0), b1=(k=kp+4, n=m0)
        uint32_t bm0[2] = { __float_as_uint(s_A[p0 * 16 + m0]),
                            __float_as_uint(s_A[(p0 + 4) * 16 + m0]) };
        uint32_t bm8[2] = { __float_as_uint(s_A[p0 * 16 + m0 + 8]),
                            __float_as_uint(s_A[(p0 + 4) * 16 + m0 + 8]) };

        mma_tf32(accR0, fc, bm0);
        mma_tf32(accR1, fc, bm8);
        mma_tf32(accI0, fs, bm0);
        mma_tf32(accI1, fs, bm8);
    }

    // ---- epilogue: C-fragment -> planar per-chunk partials ----
    // c0=(g, 2kp), c1=(g, 2kp+1), c2=(g+8, 2kp), c3=(g+8, 2kp+1)
    float* basep = g_part + (size_t)chunk * OUT_FLOATS;
#pragma unroll
    for (int mh = 0; mh < 2; ++mh) {
        const float* aR = mh ? accR1 : accR0;
        const float* aI = mh ? accI1 : accI0;
        int mcol = mh * 8 + 2 * kp;
#pragma unroll
        for (int rh = 0; rh < 2; ++rh) {
            int f = f0 + rh * 8;
            size_t o = (size_t)(b * NF + f) * NM + mcol;
            float2 vr = make_float2(aR[2 * rh], aR[2 * rh + 1]);
            float2 vi = make_float2(-aI[2 * rh], -aI[2 * rh + 1]);
            *(float2*)(basep + o) = vr;              // real plane
            *(float2*)(basep + NOUT + o) = vi;       // imag plane
        }
    }
}

// ---------- reduce stage 1: sum 16 chunks per group ----------
__global__ void __launch_bounds__(256) reduce1_kernel(void) {
    int j = blockIdx.x * 256 + threadIdx.x;
    int c0 = blockIdx.y * R1_CH;
    float s = 0.0f;
#pragma unroll
    for (int c = 0; c < R1_CH; ++c)
        s += g_part[(size_t)(c0 + c) * OUT_FLOATS + j];
    g_p2[(size_t)blockIdx.y * OUT_FLOATS + j] = s;
}

// ---------- reduce stage 2: sum 27 groups, write planar output ----------
__global__ void __launch_bounds__(256) reduce2_kernel(float* __restrict__ out, int write_imag) {
    int j = blockIdx.x * 256 + threadIdx.x;
    float s = 0.0f;
#pragma unroll
    for (int g = 0; g < R1_GROUPS; ++g)
        s += g_p2[(size_t)g * OUT_FLOATS + j];
    if (j < NOUT) out[j] = s;
    else if (write_imag) out[j] = s;
}

extern "C" void kernel_launch(void* const* d_in, const int* in_sizes, int n_in,
                              void* d_out, int out_size) {
    const float* a  = nullptr;
    const float* x  = nullptr;
    const float* aw = nullptr;
    const float* xw = nullptr;
    for (int i = 0; i < n_in; ++i) {
        switch (in_sizes[i]) {
            case SZ_A:  a  = (const float*)d_in[i]; break;
            case SZ_X:  x  = (const float*)d_in[i]; break;
            case SZ_AW: aw = (const float*)d_in[i]; break;
            case SZ_XW: xw = (const float*)d_in[i]; break;
            default: break;
        }
    }
    float* out = (float*)d_out;
    int write_imag = (out_size >= OUT_FLOATS) ? 1 : 0;

    cudaFuncSetAttribute(spectral_main,
                         cudaFuncAttributeMaxDynamicSharedMemorySize, SMEM_BYTES);

    dim3 grid(NCHUNK, BATCH * 2);
    spectral_main<<<grid, 256, SMEM_BYTES>>>(a, x, aw, xw);
    dim3 rg1(OUT_FLOATS / 256, R1_GROUPS);
    reduce1_kernel<<<rg1, 256>>>();
    reduce2_kernel<<<OUT_FLOATS / 256, 256>>>(out, write_imag);
}

// round 14
// speedup vs baseline: 1.2035x; 1.2035x over previous
#include <cuda_runtime.h>
#include <cstdint>

// ---------------- problem constants ----------------
#define BATCH   2
#define NPTS    110592            // 48^3
#define BN      (BATCH * NPTS)    // 221184
#define NF      256
#define NM      16
#define NCHUNK  432               // chunks per batch
#define CHUNK   256               // points per CTA (432 * 256 = 110592)
#define NPB     (CHUNK / 8)       // 32 point-blocks of 8
#define TWO_PI_F 6.283185307179586f
#define INV_SQRT_N 0.0030070286f  // 1/sqrt(110592)

#define NOUT       (BATCH * NF * NM)       // 8192 complex elements
#define OUT_FLOATS (NOUT * 2)              // 16384

// reduction tree: 432 = 27 * 16
#define R1_GROUPS  27
#define R1_CH      16

#define SZ_A   (BN * 16)
#define SZ_X   (BN * 3)
#define SZ_AW  (16 * 16)
#define SZ_XW  (3 * 256)

// SMEM layout (floats): aw[256] | xraw[768] | x4[1024] | A[4096]
#define SMF_AW  0
#define SMF_XR  256
#define SMF_X4  (256 + 768)
#define SMF_A   (256 + 768 + 1024)
#define SMEM_BYTES ((256 + 768 + 1024 + 4096) * 4)   // 24576

// ---------------- device scratch (no allocation allowed) ----------------
__device__ float g_part[NCHUNK * OUT_FLOATS];     // per-chunk planar partials (28.3 MB)
__device__ float g_p2[R1_GROUPS * OUT_FLOATS];    // stage-1 partials (1.8 MB)

// ---------------- helpers ----------------
__device__ __forceinline__ uint32_t tf32r(float f) {
    uint32_t r;
    asm("cvt.rna.tf32.f32 %0, %1;" : "=r"(r) : "f"(f));
    return r;
}
__device__ __forceinline__ void mma_tf32(float* d, const uint32_t* a, const uint32_t* b) {
    asm volatile(
        "mma.sync.aligned.m16n8k8.row.col.f32.tf32.tf32.f32 "
        "{%0,%1,%2,%3}, {%4,%5,%6,%7}, {%8,%9}, {%0,%1,%2,%3};"
        : "+f"(d[0]), "+f"(d[1]), "+f"(d[2]), "+f"(d[3])
        : "r"(a[0]), "r"(a[1]), "r"(a[2]), "r"(a[3]), "r"(b[0]), "r"(b[1]));
}

// ---------- fused kernel: stage + project + sincos + tf32 MMA ----------
// grid = (NCHUNK, BATCH), 256 threads; warp w covers f in [w*32, w*32+32).
// R12 fragment layout (8 MMA per 6 LDS) + small chunks for clean 2-wave balance.
__global__ void __launch_bounds__(256, 3) spectral_main(const float* __restrict__ a,
                                                        const float* __restrict__ x,
                                                        const float* __restrict__ aw,
                                                        const float* __restrict__ xw) {
    extern __shared__ float sm[];
    float*  s_aw = sm + SMF_AW;             // 16x16 row-major [i][m]
    float*  s_xr = sm + SMF_XR;             // 256 x 3 raw
    float4* s_x4 = (float4*)(sm + SMF_X4);  // 256 x float4 (padded)
    float*  s_A  = sm + SMF_A;              // 256 x 16, tf32-rounded scaled coefficients

    const int tid  = threadIdx.x;
    const int lane = tid & 31;
    const int warp = tid >> 5;
    const int b    = blockIdx.y;
    const int chunk = blockIdx.x;
    const size_t pbase = (size_t)(b * NPTS + chunk * CHUNK);

    // ---- stage: aw, raw a-chunk (16KB), raw x-chunk (3KB), all coalesced ----
    s_aw[tid] = aw[tid];
    {
        const float4* ga = (const float4*)(a + pbase * 16);   // 1024 float4
        float4* sa4 = (float4*)s_A;
#pragma unroll
        for (int i = 0; i < 4; ++i) sa4[tid + 256 * i] = ga[tid + 256 * i];
        const float4* gx = (const float4*)(x + pbase * 3);    // 192 float4
        float4* sx4 = (float4*)s_xr;
        if (tid < 192) sx4[tid] = gx[tid];
    }
    __syncthreads();

    // ---- pad x to float4: one point per thread ----
    {
        float r0 = s_xr[tid * 3 + 0], r1 = s_xr[tid * 3 + 1], r2 = s_xr[tid * 3 + 2];
        s_x4[tid] = make_float4(r0, r1, r2, 0.0f);
    }

    // ---- in-place projection: A[p][m] = tf32(sum_i a[p][i]*aw[i][m] * inv_sqrt_n)
    {
        int p = tid;
        float ai[16];
#pragma unroll
        for (int i = 0; i < 16; ++i) ai[i] = s_A[p * 16 + i];
        float o[16];
#pragma unroll
        for (int m = 0; m < 16; ++m) o[m] = 0.0f;
#pragma unroll
        for (int i = 0; i < 16; ++i)
#pragma unroll
            for (int m = 0; m < 16; ++m)
                o[m] = fmaf(ai[i], s_aw[i * 16 + m], o[m]);
#pragma unroll
        for (int m = 0; m < 16; ++m)
            s_A[p * 16 + m] = __uint_as_float(tf32r(o[m] * INV_SQRT_N));
    }
    __syncthreads();

    // ---- per-thread frequency weights (2*pi folded), 4 f's per thread ----
    const int fb = warp * 32 + (lane >> 2);
    float W[4][3];
#pragma unroll
    for (int j = 0; j < 4; ++j) {
        int f = fb + 8 * j;
        W[j][0] = TWO_PI_F * xw[f];
        W[j][1] = TWO_PI_F * xw[NF + f];
        W[j][2] = TWO_PI_F * xw[2 * NF + f];
    }

    float accR[2][2][4], accI[2][2][4];
#pragma unroll
    for (int i = 0; i < 2; ++i)
#pragma unroll
        for (int j = 0; j < 2; ++j)
#pragma unroll
            for (int k = 0; k < 4; ++k) { accR[i][j][k] = 0.0f; accI[i][j][k] = 0.0f; }

    const int kp = lane & 3;        // k-position within point-block
    const int m0 = lane >> 2;       // m channel for B fragment

    for (int pb = 0; pb < NPB; ++pb) {
        const int p0 = pb * 8 + kp;
        float4 xv0 = s_x4[p0];          // LDS.128, 4-way broadcast groups
        float4 xv1 = s_x4[p0 + 4];

        float cv[8], sv[8];             // [j*2 + psel]
#pragma unroll
        for (int j = 0; j < 4; ++j) {
            float ph0 = fmaf(xv0.x, W[j][0], fmaf(xv0.y, W[j][1], xv0.z * W[j][2]));
            float ph1 = fmaf(xv1.x, W[j][0], fmaf(xv1.y, W[j][1], xv1.z * W[j][2]));
            __sincosf(ph0, &sv[2 * j], &cv[2 * j]);
            __sincosf(ph1, &sv[2 * j + 1], &cv[2 * j + 1]);
        }

        // A fragments: raw fp32 bits (tf32 MMA HW truncates low mantissa bits)
        uint32_t fc0[4] = { __float_as_uint(cv[0]), __float_as_uint(cv[2]),
                            __float_as_uint(cv[1]), __float_as_uint(cv[3]) };
        uint32_t fs0[4] = { __float_as_uint(sv[0]), __float_as_uint(sv[2]),
                            __float_as_uint(sv[1]), __float_as_uint(sv[3]) };
        uint32_t fc1[4] = { __float_as_uint(cv[4]), __float_as_uint(cv[6]),
                            __float_as_uint(cv[5]), __float_as_uint(cv[7]) };
        uint32_t fs1[4] = { __float_as_uint(sv[4]), __float_as_uint(sv[6]),
                            __float_as_uint(sv[5]), __float_as_uint(sv[7]) };

        uint32_t bm0[2] = { __float_as_uint(s_A[p0 * 16 + m0]),
                            __float_as_uint(s_A[(p0 + 4) * 16 + m0]) };
        uint32_t bm8[2] = { __float_as_uint(s_A[p0 * 16 + m0 + 8]),
                            __float_as_uint(s_A[(p0 + 4) * 16 + m0 + 8]) };

        mma_tf32(accR[0][0], fc0, bm0);  mma_tf32(accR[0][1], fc0, bm8);
        mma_tf32(accI[0][0], fs0, bm0);  mma_tf32(accI[0][1], fs0, bm8);
        mma_tf32(accR[1][0], fc1, bm0);  mma_tf32(accR[1][1], fc1, bm8);
        mma_tf32(accI[1][0], fs1, bm0);  mma_tf32(accI[1][1], fs1, bm8);
    }

    // ---- epilogue: C-fragment -> planar per-chunk partials ----
    float* basep = g_part + (size_t)chunk * OUT_FLOATS;
#pragma unroll
    for (int ft = 0; ft < 2; ++ft) {
#pragma unroll
        for (int mh = 0; mh < 2; ++mh) {
            int mcol = mh * 8 + 2 * kp;
#pragma unroll
            for (int rh = 0; rh < 2; ++rh) {
                int f = warp * 32 + ft * 16 + (lane >> 2) + rh * 8;
                size_t o = (size_t)(b * NF + f) * NM + mcol;
                float2 vr = make_float2(accR[ft][mh][2 * rh], accR[ft][mh][2 * rh + 1]);
                float2 vi = make_float2(-accI[ft][mh][2 * rh], -accI[ft][mh][2 * rh + 1]);
                *(float2*)(basep + o) = vr;              // real plane
                *(float2*)(basep + NOUT + o) = vi;       // imag plane
            }
        }
    }
}

// ---------- reduce stage 1: sum 16 chunks per group ----------
__global__ void __launch_bounds__(256) reduce1_kernel(void) {
    int j = blockIdx.x * 256 + threadIdx.x;
    int c0 = blockIdx.y * R1_CH;
    float s = 0.0f;
#pragma unroll
    for (int c = 0; c < R1_CH; ++c)
        s += g_part[(size_t)(c0 + c) * OUT_FLOATS + j];
    g_p2[(size_t)blockIdx.y * OUT_FLOATS + j] = s;
}

// ---------- reduce stage 2: sum 27 groups, write planar output ----------
__global__ void __launch_bounds__(256) reduce2_kernel(float* __restrict__ out, int write_imag) {
    int j = blockIdx.x * 256 + threadIdx.x;
    float s = 0.0f;
#pragma unroll
    for (int g = 0; g < R1_GROUPS; ++g)
        s += g_p2[(size_t)g * OUT_FLOATS + j];
    if (j < NOUT) out[j] = s;
    else if (write_imag) out[j] = s;
}

extern "C" void kernel_launch(void* const* d_in, const int* in_sizes, int n_in,
                              void* d_out, int out_size) {
    const float* a  = nullptr;
    const float* x  = nullptr;
    const float* aw = nullptr;
    const float* xw = nullptr;
    for (int i = 0; i < n_in; ++i) {
        switch (in_sizes[i]) {
            case SZ_A:  a  = (const float*)d_in[i]; break;
            case SZ_X:  x  = (const float*)d_in[i]; break;
            case SZ_AW: aw = (const float*)d_in[i]; break;
            case SZ_XW: xw = (const float*)d_in[i]; break;
            default: break;
        }
    }
    float* out = (float*)d_out;
    int write_imag = (out_size >= OUT_FLOATS) ? 1 : 0;

    cudaFuncSetAttribute(spectral_main,
                         cudaFuncAttributeMaxDynamicSharedMemorySize, SMEM_BYTES);

    dim3 grid(NCHUNK, BATCH);
    spectral_main<<<grid, 256, SMEM_BYTES>>>(a, x, aw, xw);
    dim3 rg1(OUT_FLOATS / 256, R1_GROUPS);
    reduce1_kernel<<<rg1, 256>>>();
    reduce2_kernel<<<OUT_FLOATS / 256, 256>>>(out, write_imag);
}